// round 3
// baseline (speedup 1.0000x reference)
#include <cuda_runtime.h>
#include <cuda_bf16.h>

#define CC 40
#define ALPHA 0.5f
#define THREADS 256
#define MAX_BLOCKS 16384

__device__ float g_partials[MAX_BLOCKS];

__global__ void __launch_bounds__(THREADS)
hdl_main_kernel(const float* __restrict__ logits,
                const int*   __restrict__ labels,
                const float* __restrict__ dis,
                float* __restrict__ df_out,
                int B)
{
    __shared__ float s_dis[CC * CC];
    for (int i = threadIdx.x; i < CC * CC; i += blockDim.x)
        s_dis[i] = dis[i];
    __syncthreads();

    int row = blockIdx.x * blockDim.x + threadIdx.x;
    float local = 0.0f;

    if (row < B) {
        const float4* p = reinterpret_cast<const float4*>(logits + (size_t)row * CC);
        float4 v[10];
        #pragma unroll
        for (int i = 0; i < 10; i++) v[i] = p[i];

        float x[CC];
        #pragma unroll
        for (int i = 0; i < 10; i++) {
            x[4*i+0] = v[i].x; x[4*i+1] = v[i].y;
            x[4*i+2] = v[i].z; x[4*i+3] = v[i].w;
        }

        // max + argmax (first-max index, matching jnp.argmax)
        float m = x[0];
        int   am = 0;
        #pragma unroll
        for (int i = 1; i < CC; i++) {
            if (x[i] > m) { m = x[i]; am = i; }
        }

        // logsumexp
        float s = 0.0f;
        #pragma unroll
        for (int i = 0; i < CC; i++)
            s += expf(x[i] - m);

        int lab = labels[row];

        // extract x[lab] without dynamic register indexing
        float xl = x[0];
        #pragma unroll
        for (int i = 1; i < CC; i++)
            xl = (i == lab) ? x[i] : xl;

        float ce = (m - xl) + logf(s);
        float df = s_dis[lab * CC + am] + ALPHA;
        df_out[row] = df;
        local = ce * df;
    }

    // block reduction (fixed order)
    __shared__ float s_warp[THREADS / 32];
    #pragma unroll
    for (int o = 16; o > 0; o >>= 1)
        local += __shfl_down_sync(0xFFFFFFFFu, local, o);
    if ((threadIdx.x & 31) == 0)
        s_warp[threadIdx.x >> 5] = local;
    __syncthreads();
    if (threadIdx.x < 32) {
        float v = (threadIdx.x < THREADS / 32) ? s_warp[threadIdx.x] : 0.0f;
        #pragma unroll
        for (int o = 16; o > 0; o >>= 1)
            v += __shfl_down_sync(0xFFFFFFFFu, v, o);
        if (threadIdx.x == 0)
            g_partials[blockIdx.x] = v;
    }
}

__global__ void hdl_reduce_kernel(float* __restrict__ loss_out,
                                  int nblocks, float invB)
{
    __shared__ float s_warp[32];
    float v = 0.0f;
    for (int i = threadIdx.x; i < nblocks; i += blockDim.x)
        v += g_partials[i];
    #pragma unroll
    for (int o = 16; o > 0; o >>= 1)
        v += __shfl_down_sync(0xFFFFFFFFu, v, o);
    if ((threadIdx.x & 31) == 0)
        s_warp[threadIdx.x >> 5] = v;
    __syncthreads();
    if (threadIdx.x < 32) {
        v = (threadIdx.x < (blockDim.x >> 5)) ? s_warp[threadIdx.x] : 0.0f;
        #pragma unroll
        for (int o = 16; o > 0; o >>= 1)
            v += __shfl_down_sync(0xFFFFFFFFu, v, o);
        if (threadIdx.x == 0)
            *loss_out = v * invB;   // mean; NORMALISE == 1.0
    }
}

extern "C" void kernel_launch(void* const* d_in, const int* in_sizes, int n_in,
                              void* d_out, int out_size)
{
    const float* logits = (const float*)d_in[0];
    const int*   labels = (const int*)d_in[1];
    const float* dis    = (const float*)d_in[2];
    int B = in_sizes[1];

    float* out = (float*)d_out;
    float* loss_ptr;
    float* df_ptr;
    if (out_size > B) {            // flattened tuple: [loss, distance_factor]
        loss_ptr = out;
        df_ptr   = out + 1;
    } else {                       // fallback: df only
        loss_ptr = out;            // still write somewhere deterministic
        df_ptr   = out;
    }

    int nblocks = (B + THREADS - 1) / THREADS;
    if (nblocks > MAX_BLOCKS) nblocks = MAX_BLOCKS;   // B=2^20 -> 4096, safe

    hdl_main_kernel<<<nblocks, THREADS>>>(logits, labels, dis, df_ptr, B);
    hdl_reduce_kernel<<<1, 1024>>>(loss_ptr, nblocks, 1.0f / (float)B);
}